// round 2
// baseline (speedup 1.0000x reference)
#include <cuda_runtime.h>

// VolumeRotation: B=8, C=16, S=64
// out[b,c,z,y,x] = trilinear_sample(vol[b,c], R_b^T @ base(z,y,x)), zero padding,
// align_corners=False.

#define SB 64
#define CB 16
#define S3 (SB*SB*SB)

__global__ __launch_bounds__(256, 8)
void volrot_kernel(const float* __restrict__ vol,
                   const float* __restrict__ rot,
                   float* __restrict__ out)
{
    int idx = blockIdx.x * blockDim.x + threadIdx.x;   // 0 .. B*S3-1
    int x =  idx        & (SB-1);
    int y = (idx >> 6)  & (SB-1);
    int z = (idx >> 12) & (SB-1);
    int b =  idx >> 18;

    // normalized base coords, linspace(-1,1,64)
    const float scale = 2.0f / 63.0f;
    float bx = -1.0f + (float)x * scale;
    float by = -1.0f + (float)y * scale;
    float bz = -1.0f + (float)z * scale;

    // grid = R^T @ base  (UT[i][j] = R[j][i])
    const float* R = rot + b * 9;
    float r00 = __ldg(R+0), r01 = __ldg(R+1), r02 = __ldg(R+2);
    float r10 = __ldg(R+3), r11 = __ldg(R+4), r12 = __ldg(R+5);
    float r20 = __ldg(R+6), r21 = __ldg(R+7), r22 = __ldg(R+8);
    float gx = r00*bx + r10*by + r20*bz;
    float gy = r01*bx + r11*by + r21*bz;
    float gz = r02*bx + r12*by + r22*bz;

    // unnormalize, align_corners=False: p = (g+1)*size/2 - 0.5
    float fx = fmaf(gx, 32.0f, 31.5f);
    float fy = fmaf(gy, 32.0f, 31.5f);
    float fz = fmaf(gz, 32.0f, 31.5f);

    float x0f = floorf(fx), y0f = floorf(fy), z0f = floorf(fz);
    float tx = fx - x0f, ty = fy - y0f, tz = fz - z0f;
    int x0 = (int)x0f, y0 = (int)y0f, z0 = (int)z0f;

    float wx[2] = {1.0f - tx, tx};
    float wy[2] = {1.0f - ty, ty};
    float wz[2] = {1.0f - tz, tz};

    int   lin[8];
    float w[8];
    #pragma unroll
    for (int k = 0; k < 8; k++) {
        int dx = k & 1, dy = (k >> 1) & 1, dz = (k >> 2) & 1;
        int xi = x0 + dx, yi = y0 + dy, zi = z0 + dz;
        bool valid = ((unsigned)xi < (unsigned)SB) &
                     ((unsigned)yi < (unsigned)SB) &
                     ((unsigned)zi < (unsigned)SB);
        float ww = wx[dx] * wy[dy] * wz[dz];
        w[k] = valid ? ww : 0.0f;
        int xc = min(max(xi, 0), SB-1);
        int yc = min(max(yi, 0), SB-1);
        int zc = min(max(zi, 0), SB-1);
        lin[k] = (zc * SB + yc) * SB + xc;
    }

    const float* vb = vol + (size_t)b * CB * S3;
    float*       ob = out + (size_t)b * CB * S3 + ((z * SB + y) * SB + x);

    // channel loop: 8 gathers + 1 coalesced store each; unroll pairs for MLP
    #pragma unroll
    for (int c = 0; c < CB; c += 2) {
        const float* v0 = vb + (size_t)c * S3;
        const float* v1 = v0 + S3;
        float a0 = 0.0f, a1 = 0.0f;
        float g0[8], g1[8];
        #pragma unroll
        for (int k = 0; k < 8; k++) g0[k] = __ldg(v0 + lin[k]);
        #pragma unroll
        for (int k = 0; k < 8; k++) g1[k] = __ldg(v1 + lin[k]);
        #pragma unroll
        for (int k = 0; k < 8; k++) { a0 = fmaf(w[k], g0[k], a0); a1 = fmaf(w[k], g1[k], a1); }
        ob[(size_t)c * S3]       = a0;
        ob[(size_t)(c+1) * S3]   = a1;
    }
}

extern "C" void kernel_launch(void* const* d_in, const int* in_sizes, int n_in,
                              void* d_out, int out_size)
{
    const float* vol = (const float*)d_in[0];   // [8,16,64,64,64] f32
    const float* rot = (const float*)d_in[1];   // [8,3,3] f32
    float* out = (float*)d_out;

    int total = 8 * S3;                          // threads = spatial voxels
    volrot_kernel<<<total / 256, 256>>>(vol, rot, out);
}

// round 3
// speedup vs baseline: 1.6612x; 1.6612x over previous
#include <cuda_runtime.h>

// VolumeRotation: B=8, C=16, S=64
// out[b,c,z,y,x] = trilinear_sample(vol[b,c], R_b^T @ base(z,y,x)), zero padding,
// align_corners=False.
//
// Round 2: merge the (dx=0, dx=1) corner pair into ONE aligned float4 load per
// (dy,dz) row (4 gather instructions/channel instead of 8), with a predicated
// scalar tail load for the cA%4==3 case. Halves L1tex wavefront traffic, which
// ncu showed to be the bottleneck (L1=85%, DRAM=6%).

#define SB 64
#define CB 16
#define S3 (SB*SB*SB)

__device__ __forceinline__ float sel4(const float4 f, int m) {
    // f[m], m in 0..3
    float r = f.x;
    r = (m == 1) ? f.y : r;
    r = (m == 2) ? f.z : r;
    r = (m == 3) ? f.w : r;
    return r;
}
__device__ __forceinline__ float sel4n(const float4 f, int m, float n) {
    // f[m+1] with overflow value n, m in 0..3
    float r = f.y;
    r = (m == 1) ? f.z : r;
    r = (m == 2) ? f.w : r;
    r = (m == 3) ? n   : r;
    return r;
}

__global__ __launch_bounds__(256)
void volrot_kernel(const float* __restrict__ vol,
                   const float* __restrict__ rot,
                   float* __restrict__ out)
{
    int idx = blockIdx.x * blockDim.x + threadIdx.x;   // 0 .. B*S3-1
    int x =  idx        & (SB-1);
    int y = (idx >> 6)  & (SB-1);
    int z = (idx >> 12) & (SB-1);
    int b =  idx >> 18;

    // normalized base coords, linspace(-1,1,64)
    const float scale = 2.0f / 63.0f;
    float bx = -1.0f + (float)x * scale;
    float by = -1.0f + (float)y * scale;
    float bz = -1.0f + (float)z * scale;

    // grid = R^T @ base
    const float* R = rot + b * 9;
    float r00 = __ldg(R+0), r01 = __ldg(R+1), r02 = __ldg(R+2);
    float r10 = __ldg(R+3), r11 = __ldg(R+4), r12 = __ldg(R+5);
    float r20 = __ldg(R+6), r21 = __ldg(R+7), r22 = __ldg(R+8);
    float gx = r00*bx + r10*by + r20*bz;
    float gy = r01*bx + r11*by + r21*bz;
    float gz = r02*bx + r12*by + r22*bz;

    // unnormalize, align_corners=False: p = (g+1)*size/2 - 0.5
    float fx = fmaf(gx, 32.0f, 31.5f);
    float fy = fmaf(gy, 32.0f, 31.5f);
    float fz = fmaf(gz, 32.0f, 31.5f);

    float x0f = floorf(fx), y0f = floorf(fy), z0f = floorf(fz);
    float tx = fx - x0f, ty = fy - y0f, tz = fz - z0f;
    int x0 = (int)x0f, y0 = (int)y0f, z0 = (int)z0f;

    // ---- x pair handling (shared across all rows and channels) ----
    int cA = min(max(x0, 0), SB-1);
    int cB = min(max(x0 + 1, 0), SB-1);
    int delta = cB - cA;                       // 0 or 1
    float ex0 = ((unsigned)x0       < (unsigned)SB) ? (1.0f - tx) : 0.0f;
    float ex1 = ((unsigned)(x0 + 1) < (unsigned)SB) ? tx          : 0.0f;
    int woff = cA & ~3;                        // aligned float4 window
    int mA   = cA & 3;
    bool tail = (mA == 3) && (delta == 1);     // need element cA+1 = woff+4

    // ---- (dy,dz) rows: offsets + combined weights ----
    float wy[2] = {1.0f - ty, ty};
    float wz[2] = {1.0f - tz, tz};
    int   rowoff[4];
    float wp[4];
    #pragma unroll
    for (int j = 0; j < 4; j++) {
        int dy = j & 1, dz = j >> 1;
        int yi = y0 + dy, zi = z0 + dz;
        bool vyz = ((unsigned)yi < (unsigned)SB) & ((unsigned)zi < (unsigned)SB);
        int yc = min(max(yi, 0), SB-1);
        int zc = min(max(zi, 0), SB-1);
        rowoff[j] = (zc * SB + yc) * SB;
        wp[j] = vyz ? (wy[dy] * wz[dz]) : 0.0f;
    }

    const float* vb = vol + (size_t)b * CB * S3;
    float*       ob = out + (size_t)b * CB * S3 + ((z * SB + y) * SB + x);

    // channel loop: 4 float4 gathers (+ predicated tail) per channel
    #pragma unroll
    for (int c = 0; c < CB; c += 2) {
        const float* p0 = vb + (size_t)c * S3;
        const float* p1 = p0 + S3;
        float a0 = 0.0f, a1 = 0.0f;
        #pragma unroll
        for (int j = 0; j < 4; j++) {
            const float4 f0 = __ldg((const float4*)(p0 + rowoff[j] + woff));
            const float4 f1 = __ldg((const float4*)(p1 + rowoff[j] + woff));
            float n0 = 0.0f, n1 = 0.0f;
            if (tail) {
                n0 = __ldg(p0 + rowoff[j] + cA + 1);
                n1 = __ldg(p1 + rowoff[j] + cA + 1);
            }
            float v00 = sel4 (f0, mA);
            float v01 = delta ? sel4n(f0, mA, n0) : v00;
            float v10 = sel4 (f1, mA);
            float v11 = delta ? sel4n(f1, mA, n1) : v10;
            float s0 = ex0 * v00 + ex1 * v01;
            float s1 = ex0 * v10 + ex1 * v11;
            a0 = fmaf(wp[j], s0, a0);
            a1 = fmaf(wp[j], s1, a1);
        }
        ob[(size_t)c * S3]     = a0;
        ob[(size_t)(c+1) * S3] = a1;
    }
}

extern "C" void kernel_launch(void* const* d_in, const int* in_sizes, int n_in,
                              void* d_out, int out_size)
{
    const float* vol = (const float*)d_in[0];   // [8,16,64,64,64] f32
    const float* rot = (const float*)d_in[1];   // [8,3,3] f32
    float* out = (float*)d_out;

    int total = 8 * S3;
    volrot_kernel<<<total / 256, 256>>>(vol, rot, out);
}